// round 9
// baseline (speedup 1.0000x reference)
#include <cuda_runtime.h>

// Problem constants
#define BB   8
#define CC   64
#define NN   4096
#define KK   20
#define MM   8
#define OUTC 64
#define CKD  512      // C*M

typedef unsigned long long ull;

// ---------------------------------------------------------------------------
// f32x2 packed-math macros (sm_100+)
// ---------------------------------------------------------------------------
#define FMA2(d, a, b, c) \
    asm("fma.rn.f32x2 %0, %1, %2, %3;" : "=l"(d) : "l"(a), "l"(b), "l"(c))
#define PACK2(d, x) \
    asm("mov.b64 %0, {%1, %1};" : "=l"(d) : "r"(x))
#define UNPACK2(lo, hi, v) \
    asm("mov.b64 {%0, %1}, %2;" : "=r"(lo), "=r"(hi) : "l"(v))

// Scratch (device globals: allocation-free). 16B-aligned.
__device__ __align__(16) float g_featT[BB * NN * CC];   // (B,N,C)
__device__ __align__(16) float g_xT[BB * NN * 3];       // (B,N,3)
__device__ __align__(16) ull   g_wT2[CKD * OUTC];       // [k][oc] duplicated f32x2 pairs
__device__ __align__(16) float g_agg[BB * NN * CKD];    // (B*N, 512) agg rows
__device__ int g_is64;                                  // neigh dtype flag

// ---------------------------------------------------------------------------
// Kernel 0: probe neigh index dtype (int64 values < 4096 => odd words all 0)
// ---------------------------------------------------------------------------
__global__ void probe_idx_k(const int* __restrict__ nw) {
    __shared__ int any_nonzero;
    if (threadIdx.x == 0) any_nonzero = 0;
    __syncthreads();
    int nz = 0;
#pragma unroll
    for (int i = 0; i < 4; i++) {
        int w = nw[2 * (threadIdx.x + 256 * i) + 1];
        nz |= (w != 0);
    }
    if (nz) atomicOr(&any_nonzero, 1);
    __syncthreads();
    if (threadIdx.x == 0) g_is64 = any_nonzero ? 0 : 1;
}

// ---------------------------------------------------------------------------
// Kernel 1: transpose feature (B,C,N) -> (B,N,C), tiled 32x32
// ---------------------------------------------------------------------------
__global__ void transpose_feat_k(const float* __restrict__ f) {
    __shared__ float tile[32][33];
    int b  = blockIdx.z;
    int n0 = blockIdx.x * 32;
    int c0 = blockIdx.y * 32;
    int tx = threadIdx.x, ty = threadIdx.y;
#pragma unroll
    for (int i = ty; i < 32; i += 8)
        tile[i][tx] = f[((size_t)b * CC + c0 + i) * NN + n0 + tx];
    __syncthreads();
#pragma unroll
    for (int i = ty; i < 32; i += 8)
        g_featT[((size_t)b * NN + n0 + i) * CC + c0 + tx] = tile[tx][i];
}

// ---------------------------------------------------------------------------
// Kernel 2: x (B,3,N)->(B,N,3), conv_w (64,512) -> packed-dup (512,64) pairs
// ---------------------------------------------------------------------------
__global__ void pre_misc_k(const float* __restrict__ x, const float* __restrict__ w) {
    int t = blockIdx.x * blockDim.x + threadIdx.x;
    if (t < BB * NN) {
        int b = t / NN, n = t % NN;
#pragma unroll
        for (int c = 0; c < 3; c++)
            g_xT[(size_t)t * 3 + c] = x[((size_t)b * 3 + c) * NN + n];
    } else {
        int u = t - BB * NN;
        if (u < CKD * OUTC) {
            int k = u / OUTC, oc = u % OUTC;
            float v = w[(size_t)oc * CKD + k];
            ull pv; PACK2(pv, __float_as_uint(v));
            g_wT2[u] = pv;
        }
    }
}

// ---------------------------------------------------------------------------
// Kernel 3 (agg): one warp = 4 points. 256 threads/block = 32 points.
// Lane owns channel pair (2l, 2l+1). Per k: 1 LDG.64 + 8 broadcast LDS.64
// (pre-duplicated f32x2 softmax weights) + 8 fma.rn.f32x2.
// ---------------------------------------------------------------------------
__global__ __launch_bounds__(256) void agg_k(
    const void* __restrict__ neigh_raw,
    const float* __restrict__ kern)
{
    __shared__ __align__(16) ull psW2[8][MM * KK];   // per-warp packed weights [m][k]
    __shared__ float kerS[24];

    const int tid  = threadIdx.x;
    const int warp = tid >> 5, lane = tid & 31;

    if (tid < 24) kerS[tid] = kern[tid];
    __syncthreads();

    const int is64 = g_is64;
    const long long* n64 = (const long long*)neigh_raw;
    const int*       n32 = (const int*)neigh_raw;
    ull* psMe2 = psW2[warp];

    for (int pi = 0; pi < 4; pi++) {
        const int ng = blockIdx.x * 32 + warp * 4 + pi;   // global point
        const int b  = ng >> 12;
        const float* fbase = g_featT + (size_t)b * NN * CC;

        int j = 0;
        if (lane < KK) {
            const size_t pos = (size_t)ng * KK + lane;
            j = is64 ? (int)n64[pos] : n32[pos];
            j &= (NN - 1);
        }

        float x0 = 0.f, x1 = 0.f, x2 = 0.f;
        if (lane < KK) {
            const float* xp = g_xT + ((size_t)b * NN + j) * 3;
            x0 = xp[0]; x1 = xp[1]; x2 = xp[2];
        }
        const float c0 = __shfl_sync(0xFFFFFFFFu, x0, 0);
        const float c1 = __shfl_sync(0xFFFFFFFFu, x1, 0);
        const float c2 = __shfl_sync(0xFFFFFFFFu, x2, 0);
        x0 -= c0; x1 -= c1; x2 -= c2;

        float pr[MM];
#pragma unroll
        for (int m = 0; m < MM; m++)
            pr[m] = x0 * kerS[m] + x1 * kerS[MM + m] + x2 * kerS[2 * MM + m];
        if (lane == 0) pr[0] += 1.0f;   // one_pad before softmax

        // softmax over k (no max-sub: center point guarantees sum >= ~1,
        // arguments are O(10) so no overflow)
#pragma unroll
        for (int m = 0; m < MM; m++) {
            float e = (lane < KK) ? __expf(pr[m]) : 0.f;
            float s = e;
#pragma unroll
            for (int o = 16; o; o >>= 1)
                s += __shfl_xor_sync(0xFFFFFFFFu, s, o);
            pr[m] = e / s;
        }
        if (lane < KK) {
#pragma unroll
            for (int m = 0; m < MM; m++) {
                ull pv; PACK2(pv, __float_as_uint(pr[m]));
                psMe2[m * KK + lane] = pv;      // [m][k], 8B stride: conflict-free
            }
        }
        __syncwarp();

        int jArr[KK];
#pragma unroll
        for (int k = 0; k < KK; k++)
            jArr[k] = __shfl_sync(0xFFFFFFFFu, j, k);

        ull acc2[MM];
#pragma unroll
        for (int m = 0; m < MM; m++) acc2[m] = 0ULL;

#pragma unroll 10
        for (int k = 0; k < KK; k++) {
            const ull fv = *(const ull*)(fbase + (size_t)jArr[k] * CC + 2 * lane);
#pragma unroll
            for (int m = 0; m < MM; m++)
                FMA2(acc2[m], fv, psMe2[m * KK + k], acc2[m]);
        }

        // store agg row: ck = c*8+m. Lane l covers ck in [16l, 16l+16).
        unsigned int lo[MM], hi[MM];
#pragma unroll
        for (int m = 0; m < MM; m++) UNPACK2(lo[m], hi[m], acc2[m]);

        float* arow = g_agg + (size_t)ng * CKD + lane * 16;
        *(float4*)(arow + 0)  = make_float4(__uint_as_float(lo[0]), __uint_as_float(lo[1]),
                                            __uint_as_float(lo[2]), __uint_as_float(lo[3]));
        *(float4*)(arow + 4)  = make_float4(__uint_as_float(lo[4]), __uint_as_float(lo[5]),
                                            __uint_as_float(lo[6]), __uint_as_float(lo[7]));
        *(float4*)(arow + 8)  = make_float4(__uint_as_float(hi[0]), __uint_as_float(hi[1]),
                                            __uint_as_float(hi[2]), __uint_as_float(hi[3]));
        *(float4*)(arow + 12) = make_float4(__uint_as_float(hi[4]), __uint_as_float(hi[5]),
                                            __uint_as_float(hi[6]), __uint_as_float(hi[7]));
        __syncwarp();
    }
}

// ---------------------------------------------------------------------------
// Kernel 4 (GEMM + epilogue): out(32768x64) = agg(32768x512) @ wT(512x64),
// bias + leakyrelu + residual, output (B, OC, N).
// 512 blocks x 128 threads, 64pt x 64oc tile, thread 8pt(4 pairs) x 4oc.
// Weights pre-duplicated as f32x2 pairs => mainloop has ZERO packing movs:
// per k: 4 LDS.128 + 16 FMA2.
// ---------------------------------------------------------------------------
#define SAW 68   // sA row stride (64 + 4 pad floats)

__global__ __launch_bounds__(128) void gemm_k(
    const float* __restrict__ bias,
    const float* __restrict__ feat_orig,
    float* __restrict__ out)
{
    __shared__ __align__(16) float sA[16 * SAW];     // [k][pt]
    __shared__ __align__(16) ull   sW2[16 * OUTC];   // [k][oc] packed pairs (8KB)

    const int tid   = threadIdx.x;
    const int ptg   = tid >> 4;     // 0..7  -> pts ptg*8..+7
    const int ocg   = tid & 15;     // 0..15 -> oc  ocg*4..+3
    const int pbase = blockIdx.x * 64;
    const int b     = pbase >> 12;
    const int nbase = pbase & (NN - 1);

    ull acc[4][4];   // [oc i][pt-pair j]
#pragma unroll
    for (int i = 0; i < 4; i++)
#pragma unroll
        for (int j = 0; j < 4; j++) acc[i][j] = 0ULL;

    // staging coords: A has 256 float4 slots (2/thread), W has 512 u2 slots (4/thread)
    const int lin0 = tid, lin1 = 128 + tid;
    const int pt0 = lin0 >> 2, kq0 = lin0 & 3;
    const int pt1 = lin1 >> 2, kq1 = lin1 & 3;

    float4 pa0, pa1;
    ulonglong2 pw[4];

    // prefetch + store chunk 0
    pa0 = *(const float4*)(g_agg + (size_t)(pbase + pt0) * CKD + kq0 * 4);
    pa1 = *(const float4*)(g_agg + (size_t)(pbase + pt1) * CKD + kq1 * 4);
#pragma unroll
    for (int i = 0; i < 4; i++)
        pw[i] = ((const ulonglong2*)g_wT2)[i * 128 + tid];

    sA[(kq0 * 4 + 0) * SAW + pt0] = pa0.x; sA[(kq0 * 4 + 1) * SAW + pt0] = pa0.y;
    sA[(kq0 * 4 + 2) * SAW + pt0] = pa0.z; sA[(kq0 * 4 + 3) * SAW + pt0] = pa0.w;
    sA[(kq1 * 4 + 0) * SAW + pt1] = pa1.x; sA[(kq1 * 4 + 1) * SAW + pt1] = pa1.y;
    sA[(kq1 * 4 + 2) * SAW + pt1] = pa1.z; sA[(kq1 * 4 + 3) * SAW + pt1] = pa1.w;
#pragma unroll
    for (int i = 0; i < 4; i++)
        ((ulonglong2*)sW2)[i * 128 + tid] = pw[i];
    __syncthreads();

    for (int c = 0; c < 32; c++) {
        if (c < 31) {
            const int kc = (c + 1) * 16;
            pa0 = *(const float4*)(g_agg + (size_t)(pbase + pt0) * CKD + kc + kq0 * 4);
            pa1 = *(const float4*)(g_agg + (size_t)(pbase + pt1) * CKD + kc + kq1 * 4);
#pragma unroll
            for (int i = 0; i < 4; i++)
                pw[i] = ((const ulonglong2*)(g_wT2 + (size_t)kc * OUTC))[i * 128 + tid];
        }

#pragma unroll
        for (int k = 0; k < 16; k++) {
            const ulonglong2 qa0 = *(const ulonglong2*)(sA + k * SAW + ptg * 8);
            const ulonglong2 qa1 = *(const ulonglong2*)(sA + k * SAW + ptg * 8 + 4);
            const ulonglong2 qw0 = *(const ulonglong2*)(sW2 + k * OUTC + ocg * 4);
            const ulonglong2 qw1 = *(const ulonglong2*)(sW2 + k * OUTC + ocg * 4 + 2);
            const ull a2[4] = { qa0.x, qa0.y, qa1.x, qa1.y };
            const ull w2[4] = { qw0.x, qw0.y, qw1.x, qw1.y };
#pragma unroll
            for (int i = 0; i < 4; i++)
#pragma unroll
                for (int j = 0; j < 4; j++)
                    FMA2(acc[i][j], a2[j], w2[i], acc[i][j]);
        }

        if (c < 31) {
            __syncthreads();
            sA[(kq0 * 4 + 0) * SAW + pt0] = pa0.x; sA[(kq0 * 4 + 1) * SAW + pt0] = pa0.y;
            sA[(kq0 * 4 + 2) * SAW + pt0] = pa0.z; sA[(kq0 * 4 + 3) * SAW + pt0] = pa0.w;
            sA[(kq1 * 4 + 0) * SAW + pt1] = pa1.x; sA[(kq1 * 4 + 1) * SAW + pt1] = pa1.y;
            sA[(kq1 * 4 + 2) * SAW + pt1] = pa1.z; sA[(kq1 * 4 + 3) * SAW + pt1] = pa1.w;
#pragma unroll
            for (int i = 0; i < 4; i++)
                ((ulonglong2*)sW2)[i * 128 + tid] = pw[i];
            __syncthreads();
        }
    }

    // epilogue: bias + leaky relu + residual; out layout (B, OC, N)
#pragma unroll
    for (int i = 0; i < 4; i++) {
        const int oc = ocg * 4 + i;
        const float bv = __ldg(bias + oc);
        const size_t rowo = ((size_t)b * OUTC + oc) * NN + nbase + ptg * 8;
#pragma unroll
        for (int j = 0; j < 4; j++) {
            unsigned int lo, hi;
            UNPACK2(lo, hi, acc[i][j]);
            float v0 = __uint_as_float(lo) + bv;
            float v1 = __uint_as_float(hi) + bv;
            v0 = (v0 > 0.f) ? v0 : 0.2f * v0;
            v1 = (v1 > 0.f) ? v1 : 0.2f * v1;
            const float2 fr = *(const float2*)(feat_orig + rowo + 2 * j);
            *(float2*)(out + rowo + 2 * j) = make_float2(v0 + fr.x, v1 + fr.y);
        }
    }
}

// ---------------------------------------------------------------------------
extern "C" void kernel_launch(void* const* d_in, const int* in_sizes, int n_in,
                              void* d_out, int out_size) {
    const float* x       = (const float*)d_in[0];
    const float* feature = (const float*)d_in[1];
    const void*  neigh   = d_in[2];
    const float* kern    = (const float*)d_in[3];
    const float* conv_w  = (const float*)d_in[4];
    const float* conv_b  = (const float*)d_in[5];
    float*       out     = (float*)d_out;

    probe_idx_k<<<1, 256>>>((const int*)neigh);

    dim3 tg(NN / 32, CC / 32, BB);
    transpose_feat_k<<<tg, dim3(32, 8)>>>(feature);

    const int pre_total = BB * NN + CKD * OUTC;
    pre_misc_k<<<(pre_total + 255) / 256, 256>>>(x, conv_w);

    agg_k<<<BB * NN / 32, 256>>>(neigh, kern);

    gemm_k<<<BB * NN / 64, 128>>>(conv_b, feature, out);
}

// round 11
// speedup vs baseline: 1.4550x; 1.4550x over previous
#include <cuda_runtime.h>

// Problem constants
#define BB   8
#define CC   64
#define NN   4096
#define KK   20
#define MM   8
#define OUTC 64
#define CKD  512      // C*M

typedef unsigned long long ull;

// ---------------------------------------------------------------------------
// f32x2 packed-math macros (sm_100+)
// ---------------------------------------------------------------------------
#define FMA2(d, a, b, c) \
    asm("fma.rn.f32x2 %0, %1, %2, %3;" : "=l"(d) : "l"(a), "l"(b), "l"(c))
#define PACK2(d, x) \
    asm("mov.b64 %0, {%1, %1};" : "=l"(d) : "r"(x))
#define UNPACK2(lo, hi, v) \
    asm("mov.b64 {%0, %1}, %2;" : "=r"(lo), "=r"(hi) : "l"(v))

// Scratch (device globals: allocation-free). 16B-aligned.
__device__ __align__(16) float g_featT[BB * NN * CC];   // (B,N,C)
__device__ __align__(16) float g_xT[BB * NN * 3];       // (B,N,3)
__device__ __align__(16) float g_wT[CKD * OUTC];        // (512,64) = conv_w^T
__device__ __align__(16) float g_agg[BB * NN * CKD];    // (B*N, 512) agg rows
__device__ int g_is64;                                  // neigh dtype flag

// ---------------------------------------------------------------------------
// Kernel 0: probe neigh index dtype (int64 values < 4096 => odd words all 0)
// ---------------------------------------------------------------------------
__global__ void probe_idx_k(const int* __restrict__ nw) {
    __shared__ int any_nonzero;
    if (threadIdx.x == 0) any_nonzero = 0;
    __syncthreads();
    int nz = 0;
#pragma unroll
    for (int i = 0; i < 4; i++) {
        int w = nw[2 * (threadIdx.x + 256 * i) + 1];
        nz |= (w != 0);
    }
    if (nz) atomicOr(&any_nonzero, 1);
    __syncthreads();
    if (threadIdx.x == 0) g_is64 = any_nonzero ? 0 : 1;
}

// ---------------------------------------------------------------------------
// Kernel 1: transpose feature (B,C,N) -> (B,N,C), tiled 32x32
// ---------------------------------------------------------------------------
__global__ void transpose_feat_k(const float* __restrict__ f) {
    __shared__ float tile[32][33];
    int b  = blockIdx.z;
    int n0 = blockIdx.x * 32;
    int c0 = blockIdx.y * 32;
    int tx = threadIdx.x, ty = threadIdx.y;
#pragma unroll
    for (int i = ty; i < 32; i += 8)
        tile[i][tx] = f[((size_t)b * CC + c0 + i) * NN + n0 + tx];
    __syncthreads();
#pragma unroll
    for (int i = ty; i < 32; i += 8)
        g_featT[((size_t)b * NN + n0 + i) * CC + c0 + tx] = tile[tx][i];
}

// ---------------------------------------------------------------------------
// Kernel 2: x (B,3,N)->(B,N,3), conv_w (64,512)->(512,64)
// ---------------------------------------------------------------------------
__global__ void pre_misc_k(const float* __restrict__ x, const float* __restrict__ w) {
    int t = blockIdx.x * blockDim.x + threadIdx.x;
    if (t < BB * NN) {
        int b = t / NN, n = t % NN;
#pragma unroll
        for (int c = 0; c < 3; c++)
            g_xT[(size_t)t * 3 + c] = x[((size_t)b * 3 + c) * NN + n];
    } else {
        int u = t - BB * NN;
        if (u < CKD * OUTC) {
            int k = u / OUTC, oc = u % OUTC;
            g_wT[u] = w[(size_t)oc * CKD + k];
        }
    }
}

// ---------------------------------------------------------------------------
// Kernel 3 (agg): one warp = 4 points. 256 threads/block = 32 points.
// R8 structure (scalar FFMA aggregation, 2 LDS.128/k), with:
//  - softmax without max-subtraction (center point anchors the denominator)
//  - neighbor ids in shared (saves 20 shfl/point and ~18 registers)
// ---------------------------------------------------------------------------
__global__ __launch_bounds__(256, 5) void agg_k(
    const void* __restrict__ neigh_raw,
    const float* __restrict__ kern)
{
    __shared__ __align__(16) float psW[8][KK * MM];   // per-warp softmax matrix [k][m]
    __shared__ int   sj[8][KK];                        // per-warp neighbor ids
    __shared__ float kerS[24];

    const int tid  = threadIdx.x;
    const int warp = tid >> 5, lane = tid & 31;

    if (tid < 24) kerS[tid] = kern[tid];
    __syncthreads();

    const int is64 = g_is64;
    const long long* n64 = (const long long*)neigh_raw;
    const int*       n32 = (const int*)neigh_raw;
    float* psMe = psW[warp];
    int*   sjMe = sj[warp];

    for (int pi = 0; pi < 4; pi++) {
        const int ng = blockIdx.x * 32 + warp * 4 + pi;   // global point
        const int b  = ng >> 12;
        const float* fbase = g_featT + (size_t)b * NN * CC;

        int j = 0;
        if (lane < KK) {
            const size_t pos = (size_t)ng * KK + lane;
            j = is64 ? (int)n64[pos] : n32[pos];
            j &= (NN - 1);
            sjMe[lane] = j;
        }

        float x0 = 0.f, x1 = 0.f, x2 = 0.f;
        if (lane < KK) {
            const float* xp = g_xT + ((size_t)b * NN + j) * 3;
            x0 = xp[0]; x1 = xp[1]; x2 = xp[2];
        }
        const float c0 = __shfl_sync(0xFFFFFFFFu, x0, 0);
        const float c1 = __shfl_sync(0xFFFFFFFFu, x1, 0);
        const float c2 = __shfl_sync(0xFFFFFFFFu, x2, 0);
        x0 -= c0; x1 -= c1; x2 -= c2;

        float pr[MM];
#pragma unroll
        for (int m = 0; m < MM; m++)
            pr[m] = x0 * kerS[m] + x1 * kerS[MM + m] + x2 * kerS[2 * MM + m];
        if (lane == 0) pr[0] += 1.0f;   // one_pad before softmax

        // softmax over k, no max-sub (center point contributes exp(0)=1;
        // validated rel_err ~1e-7 in earlier round)
#pragma unroll
        for (int m = 0; m < MM; m++) {
            float e = (lane < KK) ? __expf(pr[m]) : 0.f;
            float s = e;
#pragma unroll
            for (int o = 16; o; o >>= 1)
                s += __shfl_xor_sync(0xFFFFFFFFu, s, o);
            pr[m] = e / s;
        }
        if (lane < KK) {
#pragma unroll
            for (int m = 0; m < MM; m++) psMe[lane * MM + m] = pr[m];
        }
        __syncwarp();

        // aggregation: lane owns channels lane and lane+32
        float acc0[MM], acc1[MM];
#pragma unroll
        for (int m = 0; m < MM; m++) { acc0[m] = 0.f; acc1[m] = 0.f; }

#pragma unroll 5
        for (int k = 0; k < KK; k++) {
            const int jk = sjMe[k];                       // broadcast LDS
            const float* fr = fbase + (size_t)jk * CC;
            const float f0 = __ldg(fr + lane);
            const float f1 = __ldg(fr + lane + 32);
            const float4 pA = *(const float4*)(psMe + k * MM);
            const float4 pB = *(const float4*)(psMe + k * MM + 4);
            acc0[0] = fmaf(f0, pA.x, acc0[0]); acc0[1] = fmaf(f0, pA.y, acc0[1]);
            acc0[2] = fmaf(f0, pA.z, acc0[2]); acc0[3] = fmaf(f0, pA.w, acc0[3]);
            acc0[4] = fmaf(f0, pB.x, acc0[4]); acc0[5] = fmaf(f0, pB.y, acc0[5]);
            acc0[6] = fmaf(f0, pB.z, acc0[6]); acc0[7] = fmaf(f0, pB.w, acc0[7]);
            acc1[0] = fmaf(f1, pA.x, acc1[0]); acc1[1] = fmaf(f1, pA.y, acc1[1]);
            acc1[2] = fmaf(f1, pA.z, acc1[2]); acc1[3] = fmaf(f1, pA.w, acc1[3]);
            acc1[4] = fmaf(f1, pB.x, acc1[4]); acc1[5] = fmaf(f1, pB.y, acc1[5]);
            acc1[6] = fmaf(f1, pB.z, acc1[6]); acc1[7] = fmaf(f1, pB.w, acc1[7]);
        }

        // store agg row (ck = c*8 + m, c-major) — float4 coalesced
        float* arow = g_agg + (size_t)ng * CKD;
        *(float4*)(arow + lane * MM)            = make_float4(acc0[0], acc0[1], acc0[2], acc0[3]);
        *(float4*)(arow + lane * MM + 4)        = make_float4(acc0[4], acc0[5], acc0[6], acc0[7]);
        *(float4*)(arow + (lane + 32) * MM)     = make_float4(acc1[0], acc1[1], acc1[2], acc1[3]);
        *(float4*)(arow + (lane + 32) * MM + 4) = make_float4(acc1[4], acc1[5], acc1[6], acc1[7]);
        __syncwarp();
    }
}

// ---------------------------------------------------------------------------
// Kernel 4 (GEMM + epilogue): out(32768x64) = agg(32768x512) @ wT(512x64),
// bias + leakyrelu + residual, output (B, OC, N). R8 structure, chunk 16->32.
// 512 blocks x 128 threads, 64pt x 64oc tile, thread 8pt(4 pairs) x 4oc.
// ---------------------------------------------------------------------------
#define SAW 68   // sA row stride (64 + 4 pad floats)
#define KCH 32   // k-chunk

__global__ __launch_bounds__(128) void gemm_k(
    const float* __restrict__ bias,
    const float* __restrict__ feat_orig,
    float* __restrict__ out)
{
    __shared__ __align__(16) float sA[KCH * SAW];    // [k][pt]  (8.7 KB)
    __shared__ __align__(16) float sW[KCH * OUTC];   // [k][oc]  (8 KB)

    const int tid   = threadIdx.x;
    const int ptg   = tid >> 4;     // 0..7  -> pts ptg*8..+7
    const int ocg   = tid & 15;     // 0..15 -> oc  ocg*4..+3
    const int pbase = blockIdx.x * 64;
    const int b     = pbase >> 12;
    const int nbase = pbase & (NN - 1);

    ull acc[4][4];   // [oc i][pt-pair j]
#pragma unroll
    for (int i = 0; i < 4; i++)
#pragma unroll
        for (int j = 0; j < 4; j++) acc[i][j] = 0ULL;

    // staging: A has 64pt x 8 kq float4 slots = 512 (4/thread);
    //          W has KCH*OUTC/4 = 512 float4 slots (4/thread)
    int ptA[4], kqA[4];
#pragma unroll
    for (int i = 0; i < 4; i++) {
        const int lin = i * 128 + tid;
        ptA[i] = lin >> 3;        // 0..63
        kqA[i] = lin & 7;         // 0..7  (k quad within chunk)
    }

    float4 pa[4], pw[4];
    // prefetch chunk 0
#pragma unroll
    for (int i = 0; i < 4; i++) {
        pa[i] = *(const float4*)(g_agg + (size_t)(pbase + ptA[i]) * CKD + kqA[i] * 4);
        pw[i] = ((const float4*)g_wT)[i * 128 + tid];
    }
    // store chunk 0
#pragma unroll
    for (int i = 0; i < 4; i++) {
        sA[(kqA[i] * 4 + 0) * SAW + ptA[i]] = pa[i].x;
        sA[(kqA[i] * 4 + 1) * SAW + ptA[i]] = pa[i].y;
        sA[(kqA[i] * 4 + 2) * SAW + ptA[i]] = pa[i].z;
        sA[(kqA[i] * 4 + 3) * SAW + ptA[i]] = pa[i].w;
        ((float4*)sW)[i * 128 + tid] = pw[i];
    }
    __syncthreads();

    for (int c = 0; c < CKD / KCH; c++) {
        if (c < CKD / KCH - 1) {
            const int kc = (c + 1) * KCH;
#pragma unroll
            for (int i = 0; i < 4; i++) {
                pa[i] = *(const float4*)(g_agg + (size_t)(pbase + ptA[i]) * CKD + kc + kqA[i] * 4);
                pw[i] = ((const float4*)(g_wT + (size_t)kc * OUTC))[i * 128 + tid];
            }
        }

#pragma unroll
        for (int k = 0; k < KCH; k++) {
            const ulonglong2 qa0 = *(const ulonglong2*)(sA + k * SAW + ptg * 8);
            const ulonglong2 qa1 = *(const ulonglong2*)(sA + k * SAW + ptg * 8 + 4);
            const ull a2[4] = { qa0.x, qa0.y, qa1.x, qa1.y };
            const float4 wv = *(const float4*)(sW + k * OUTC + ocg * 4);
            ull w2[4];
            PACK2(w2[0], __float_as_uint(wv.x));
            PACK2(w2[1], __float_as_uint(wv.y));
            PACK2(w2[2], __float_as_uint(wv.z));
            PACK2(w2[3], __float_as_uint(wv.w));
#pragma unroll
            for (int i = 0; i < 4; i++)
#pragma unroll
                for (int j = 0; j < 4; j++)
                    FMA2(acc[i][j], a2[j], w2[i], acc[i][j]);
        }

        if (c < CKD / KCH - 1) {
            __syncthreads();
#pragma unroll
            for (int i = 0; i < 4; i++) {
                sA[(kqA[i] * 4 + 0) * SAW + ptA[i]] = pa[i].x;
                sA[(kqA[i] * 4 + 1) * SAW + ptA[i]] = pa[i].y;
                sA[(kqA[i] * 4 + 2) * SAW + ptA[i]] = pa[i].z;
                sA[(kqA[i] * 4 + 3) * SAW + ptA[i]] = pa[i].w;
                ((float4*)sW)[i * 128 + tid] = pw[i];
            }
            __syncthreads();
        }
    }

    // epilogue: bias + leaky relu + residual; out layout (B, OC, N)
#pragma unroll
    for (int i = 0; i < 4; i++) {
        const int oc = ocg * 4 + i;
        const float bv = __ldg(bias + oc);
        const size_t rowo = ((size_t)b * OUTC + oc) * NN + nbase + ptg * 8;
#pragma unroll
        for (int j = 0; j < 4; j++) {
            unsigned int lo, hi;
            UNPACK2(lo, hi, acc[i][j]);
            float v0 = __uint_as_float(lo) + bv;
            float v1 = __uint_as_float(hi) + bv;
            v0 = (v0 > 0.f) ? v0 : 0.2f * v0;
            v1 = (v1 > 0.f) ? v1 : 0.2f * v1;
            const float2 fr = *(const float2*)(feat_orig + rowo + 2 * j);
            *(float2*)(out + rowo + 2 * j) = make_float2(v0 + fr.x, v1 + fr.y);
        }
    }
}

// ---------------------------------------------------------------------------
extern "C" void kernel_launch(void* const* d_in, const int* in_sizes, int n_in,
                              void* d_out, int out_size) {
    const float* x       = (const float*)d_in[0];
    const float* feature = (const float*)d_in[1];
    const void*  neigh   = d_in[2];
    const float* kern    = (const float*)d_in[3];
    const float* conv_w  = (const float*)d_in[4];
    const float* conv_b  = (const float*)d_in[5];
    float*       out     = (float*)d_out;

    probe_idx_k<<<1, 256>>>((const int*)neigh);

    dim3 tg(NN / 32, CC / 32, BB);
    transpose_feat_k<<<tg, dim3(32, 8)>>>(feature);

    const int pre_total = BB * NN + CKD * OUTC;
    pre_misc_k<<<(pre_total + 255) / 256, 256>>>(x, conv_w);

    agg_k<<<BB * NN / 32, 256>>>(neigh, kern);

    gemm_k<<<BB * NN / 64, 128>>>(conv_b, feature, out);
}

// round 12
// speedup vs baseline: 1.5261x; 1.0489x over previous
#include <cuda_runtime.h>

// Problem constants
#define BB   8
#define CC   64
#define NN   4096
#define KK   20
#define MM   8
#define OUTC 64
#define CKD  512      // C*M

typedef unsigned long long ull;

// ---------------------------------------------------------------------------
// f32x2 packed-math macros (sm_100+)
// ---------------------------------------------------------------------------
#define FMA2(d, a, b, c) \
    asm("fma.rn.f32x2 %0, %1, %2, %3;" : "=l"(d) : "l"(a), "l"(b), "l"(c))
#define PACK2(d, x) \
    asm("mov.b64 %0, {%1, %1};" : "=l"(d) : "r"(x))
#define UNPACK2(lo, hi, v) \
    asm("mov.b64 {%0, %1}, %2;" : "=r"(lo), "=r"(hi) : "l"(v))

// Scratch (device globals: allocation-free). 16B-aligned.
__device__ __align__(16) float g_featT[BB * NN * CC];   // (B,N,C)
__device__ __align__(16) float g_xT[BB * NN * 3];       // (B,N,3)
__device__ __align__(16) float g_wT[CKD * OUTC];        // (512,64) = conv_w^T
__device__ __align__(16) float g_agg[BB * NN * CKD];    // (B*N, 512) agg rows
__device__ int g_is64;                                  // neigh dtype flag

// ---------------------------------------------------------------------------
// Kernel 1 (prep, fused): role dispatch by blockIdx.x
//   [0, 2048)        : transpose feature (B,C,N)->(B,N,C), 32x32 tiles
//   [2048, 2304)     : x (B,3,N)->(B,N,3) and conv_w (64,512)->(512,64)
//   [2304]           : neigh dtype probe
// ---------------------------------------------------------------------------
#define TBLK 2048
#define MBLK 256

__global__ __launch_bounds__(256) void prep_k(
    const float* __restrict__ f,
    const float* __restrict__ x,
    const float* __restrict__ w,
    const int*   __restrict__ nw)
{
    __shared__ float tile[32][33];
    __shared__ int any_nonzero;
    const int bidx = blockIdx.x;
    const int tid  = threadIdx.x;

    if (bidx < TBLK) {
        // transpose feature
        const int bx = bidx & 127, by = (bidx >> 7) & 1, bz = bidx >> 8;
        const int n0 = bx * 32, c0 = by * 32;
        const int tx = tid & 31, ty = tid >> 5;
#pragma unroll
        for (int i = ty; i < 32; i += 8)
            tile[i][tx] = f[((size_t)bz * CC + c0 + i) * NN + n0 + tx];
        __syncthreads();
#pragma unroll
        for (int i = ty; i < 32; i += 8)
            g_featT[((size_t)bz * NN + n0 + i) * CC + c0 + tx] = tile[tx][i];
    } else if (bidx < TBLK + MBLK) {
        const int t = (bidx - TBLK) * 256 + tid;
        if (t < BB * NN) {
            const int b = t / NN, n = t % NN;
#pragma unroll
            for (int c = 0; c < 3; c++)
                g_xT[(size_t)t * 3 + c] = x[((size_t)b * 3 + c) * NN + n];
        } else {
            const int u = t - BB * NN;
            if (u < CKD * OUTC) {
                const int k = u / OUTC, oc = u % OUTC;
                g_wT[u] = w[(size_t)oc * CKD + k];
            }
        }
    } else {
        // probe: int64 values < 4096 => all odd 32-bit words zero
        if (tid == 0) any_nonzero = 0;
        __syncthreads();
        int nz = 0;
#pragma unroll
        for (int i = 0; i < 4; i++) {
            const int wv = nw[2 * (tid + 256 * i) + 1];
            nz |= (wv != 0);
        }
        if (nz) atomicOr(&any_nonzero, 1);
        __syncthreads();
        if (tid == 0) g_is64 = any_nonzero ? 0 : 1;
    }
}

// ---------------------------------------------------------------------------
// Kernel 2 (agg): one warp = 4 points, processed as 2 PAIRS.
// Pairing doubles softmax ILP (two independent shfl/exp chains) and gather
// MLP (two independent float2 LDGs per k). Lane owns channels (2l, 2l+1).
// Softmax without max-subtraction (center point contributes exp(0)=1;
// validated rel_err ~1e-7).
// ---------------------------------------------------------------------------
__global__ __launch_bounds__(256, 4) void agg_k(
    const void* __restrict__ neigh_raw,
    const float* __restrict__ kern)
{
    __shared__ __align__(16) float psW[8][2][KK * MM];  // [warp][pt-in-pair][k][m]
    __shared__ int   sj[8][2][KK];
    __shared__ float kerS[24];

    const int tid  = threadIdx.x;
    const int warp = tid >> 5, lane = tid & 31;

    if (tid < 24) kerS[tid] = kern[tid];
    __syncthreads();

    const int is64 = g_is64;
    const long long* n64 = (const long long*)neigh_raw;
    const int*       n32 = (const int*)neigh_raw;

    float* psM0 = psW[warp][0];
    float* psM1 = psW[warp][1];
    int*   sj0  = sj[warp][0];
    int*   sj1  = sj[warp][1];

    for (int pp = 0; pp < 2; pp++) {
        const int ng0 = blockIdx.x * 32 + warp * 4 + pp * 2;  // even
        const int ng1 = ng0 + 1;                              // same batch (ng0 even)
        const int b   = ng0 >> 12;
        const float* fbase = g_featT + (size_t)b * NN * CC;

        int j0 = 0, j1 = 0;
        if (lane < KK) {
            const size_t pos0 = (size_t)ng0 * KK + lane;
            const size_t pos1 = (size_t)ng1 * KK + lane;
            j0 = is64 ? (int)n64[pos0] : n32[pos0];
            j1 = is64 ? (int)n64[pos1] : n32[pos1];
            j0 &= (NN - 1); j1 &= (NN - 1);
            sj0[lane] = j0; sj1[lane] = j1;
        }

        float a0 = 0.f, a1 = 0.f, a2 = 0.f;   // point0 neighbor coords
        float b0 = 0.f, b1 = 0.f, b2 = 0.f;   // point1 neighbor coords
        if (lane < KK) {
            const float* xp0 = g_xT + ((size_t)b * NN + j0) * 3;
            const float* xp1 = g_xT + ((size_t)b * NN + j1) * 3;
            a0 = xp0[0]; a1 = xp0[1]; a2 = xp0[2];
            b0 = xp1[0]; b1 = xp1[1]; b2 = xp1[2];
        }
        const float ca0 = __shfl_sync(0xFFFFFFFFu, a0, 0);
        const float ca1 = __shfl_sync(0xFFFFFFFFu, a1, 0);
        const float ca2 = __shfl_sync(0xFFFFFFFFu, a2, 0);
        const float cb0 = __shfl_sync(0xFFFFFFFFu, b0, 0);
        const float cb1 = __shfl_sync(0xFFFFFFFFu, b1, 0);
        const float cb2 = __shfl_sync(0xFFFFFFFFu, b2, 0);
        a0 -= ca0; a1 -= ca1; a2 -= ca2;
        b0 -= cb0; b1 -= cb1; b2 -= cb2;

        float pr0[MM], pr1[MM];
#pragma unroll
        for (int m = 0; m < MM; m++) {
            pr0[m] = a0 * kerS[m] + a1 * kerS[MM + m] + a2 * kerS[2 * MM + m];
            pr1[m] = b0 * kerS[m] + b1 * kerS[MM + m] + b2 * kerS[2 * MM + m];
        }
        if (lane == 0) { pr0[0] += 1.0f; pr1[0] += 1.0f; }

        // softmax over k for both points, interleaved chains
#pragma unroll
        for (int m = 0; m < MM; m++) {
            float e0 = (lane < KK) ? __expf(pr0[m]) : 0.f;
            float e1 = (lane < KK) ? __expf(pr1[m]) : 0.f;
            float s0 = e0, s1 = e1;
#pragma unroll
            for (int o = 16; o; o >>= 1) {
                s0 += __shfl_xor_sync(0xFFFFFFFFu, s0, o);
                s1 += __shfl_xor_sync(0xFFFFFFFFu, s1, o);
            }
            pr0[m] = e0 / s0;
            pr1[m] = e1 / s1;
        }
        if (lane < KK) {
#pragma unroll
            for (int m = 0; m < MM; m++) {
                psM0[lane * MM + m] = pr0[m];
                psM1[lane * MM + m] = pr1[m];
            }
        }
        __syncwarp();

        // aggregation: lane owns channels (2l, 2l+1) for BOTH points
        float accA0[MM], accB0[MM], accA1[MM], accB1[MM];
#pragma unroll
        for (int m = 0; m < MM; m++) {
            accA0[m] = 0.f; accB0[m] = 0.f; accA1[m] = 0.f; accB1[m] = 0.f;
        }

#pragma unroll 4
        for (int k = 0; k < KK; k++) {
            const int jk0 = sj0[k];
            const int jk1 = sj1[k];
            const float2 fv0 = *(const float2*)(fbase + (size_t)jk0 * CC + 2 * lane);
            const float2 fv1 = *(const float2*)(fbase + (size_t)jk1 * CC + 2 * lane);
            const float4 pA0 = *(const float4*)(psM0 + k * MM);
            const float4 pB0 = *(const float4*)(psM0 + k * MM + 4);
            const float4 pA1 = *(const float4*)(psM1 + k * MM);
            const float4 pB1 = *(const float4*)(psM1 + k * MM + 4);
            accA0[0] = fmaf(fv0.x, pA0.x, accA0[0]); accA0[1] = fmaf(fv0.x, pA0.y, accA0[1]);
            accA0[2] = fmaf(fv0.x, pA0.z, accA0[2]); accA0[3] = fmaf(fv0.x, pA0.w, accA0[3]);
            accA0[4] = fmaf(fv0.x, pB0.x, accA0[4]); accA0[5] = fmaf(fv0.x, pB0.y, accA0[5]);
            accA0[6] = fmaf(fv0.x, pB0.z, accA0[6]); accA0[7] = fmaf(fv0.x, pB0.w, accA0[7]);
            accB0[0] = fmaf(fv0.y, pA0.x, accB0[0]); accB0[1] = fmaf(fv0.y, pA0.y, accB0[1]);
            accB0[2] = fmaf(fv0.y, pA0.z, accB0[2]); accB0[3] = fmaf(fv0.y, pA0.w, accB0[3]);
            accB0[4] = fmaf(fv0.y, pB0.x, accB0[4]); accB0[5] = fmaf(fv0.y, pB0.y, accB0[5]);
            accB0[6] = fmaf(fv0.y, pB0.z, accB0[6]); accB0[7] = fmaf(fv0.y, pB0.w, accB0[7]);
            accA1[0] = fmaf(fv1.x, pA1.x, accA1[0]); accA1[1] = fmaf(fv1.x, pA1.y, accA1[1]);
            accA1[2] = fmaf(fv1.x, pA1.z, accA1[2]); accA1[3] = fmaf(fv1.x, pA1.w, accA1[3]);
            accA1[4] = fmaf(fv1.x, pB1.x, accA1[4]); accA1[5] = fmaf(fv1.x, pB1.y, accA1[5]);
            accA1[6] = fmaf(fv1.x, pB1.z, accA1[6]); accA1[7] = fmaf(fv1.x, pB1.w, accA1[7]);
            accB1[0] = fmaf(fv1.y, pA1.x, accB1[0]); accB1[1] = fmaf(fv1.y, pA1.y, accB1[1]);
            accB1[2] = fmaf(fv1.y, pA1.z, accB1[2]); accB1[3] = fmaf(fv1.y, pA1.w, accB1[3]);
            accB1[4] = fmaf(fv1.y, pB1.x, accB1[4]); accB1[5] = fmaf(fv1.y, pB1.y, accB1[5]);
            accB1[6] = fmaf(fv1.y, pB1.z, accB1[6]); accB1[7] = fmaf(fv1.y, pB1.w, accB1[7]);
        }

        // store: ck = c*8+m; lane covers ck in [16l, 16l+16) per point
        float* ar0 = g_agg + (size_t)ng0 * CKD + lane * 16;
        float* ar1 = g_agg + (size_t)ng1 * CKD + lane * 16;
        *(float4*)(ar0 + 0)  = make_float4(accA0[0], accA0[1], accA0[2], accA0[3]);
        *(float4*)(ar0 + 4)  = make_float4(accA0[4], accA0[5], accA0[6], accA0[7]);
        *(float4*)(ar0 + 8)  = make_float4(accB0[0], accB0[1], accB0[2], accB0[3]);
        *(float4*)(ar0 + 12) = make_float4(accB0[4], accB0[5], accB0[6], accB0[7]);
        *(float4*)(ar1 + 0)  = make_float4(accA1[0], accA1[1], accA1[2], accA1[3]);
        *(float4*)(ar1 + 4)  = make_float4(accA1[4], accA1[5], accA1[6], accA1[7]);
        *(float4*)(ar1 + 8)  = make_float4(accB1[0], accB1[1], accB1[2], accB1[3]);
        *(float4*)(ar1 + 12) = make_float4(accB1[4], accB1[5], accB1[6], accB1[7]);
        __syncwarp();
    }
}

// ---------------------------------------------------------------------------
// Kernel 3 (GEMM + epilogue): unchanged from R11 (best): 512 blocks x 128 thr,
// 64pt x 64oc tile, thread 8pt(4 pairs) x 4oc, KCH=32, f32x2 accumulators.
// ---------------------------------------------------------------------------
#define SAW 68   // sA row stride (64 + 4 pad floats)
#define KCH 32   // k-chunk

__global__ __launch_bounds__(128) void gemm_k(
    const float* __restrict__ bias,
    const float* __restrict__ feat_orig,
    float* __restrict__ out)
{
    __shared__ __align__(16) float sA[KCH * SAW];    // [k][pt]
    __shared__ __align__(16) float sW[KCH * OUTC];   // [k][oc]

    const int tid   = threadIdx.x;
    const int ptg   = tid >> 4;
    const int ocg   = tid & 15;
    const int pbase = blockIdx.x * 64;
    const int b     = pbase >> 12;
    const int nbase = pbase & (NN - 1);

    ull acc[4][4];
#pragma unroll
    for (int i = 0; i < 4; i++)
#pragma unroll
        for (int j = 0; j < 4; j++) acc[i][j] = 0ULL;

    int ptA[4], kqA[4];
#pragma unroll
    for (int i = 0; i < 4; i++) {
        const int lin = i * 128 + tid;
        ptA[i] = lin >> 3;
        kqA[i] = lin & 7;
    }

    float4 pa[4], pw[4];
#pragma unroll
    for (int i = 0; i < 4; i++) {
        pa[i] = *(const float4*)(g_agg + (size_t)(pbase + ptA[i]) * CKD + kqA[i] * 4);
        pw[i] = ((const float4*)g_wT)[i * 128 + tid];
    }
#pragma unroll
    for (int i = 0; i < 4; i++) {
        sA[(kqA[i] * 4 + 0) * SAW + ptA[i]] = pa[i].x;
        sA[(kqA[i] * 4 + 1) * SAW + ptA[i]] = pa[i].y;
        sA[(kqA[i] * 4 + 2) * SAW + ptA[i]] = pa[i].z;
        sA[(kqA[i] * 4 + 3) * SAW + ptA[i]] = pa[i].w;
        ((float4*)sW)[i * 128 + tid] = pw[i];
    }
    __syncthreads();

    for (int c = 0; c < CKD / KCH; c++) {
        if (c < CKD / KCH - 1) {
            const int kc = (c + 1) * KCH;
#pragma unroll
            for (int i = 0; i < 4; i++) {
                pa[i] = *(const float4*)(g_agg + (size_t)(pbase + ptA[i]) * CKD + kc + kqA[i] * 4);
                pw[i] = ((const float4*)(g_wT + (size_t)kc * OUTC))[i * 128 + tid];
            }
        }

#pragma unroll
        for (int k = 0; k < KCH; k++) {
            const ulonglong2 qa0 = *(const ulonglong2*)(sA + k * SAW + ptg * 8);
            const ulonglong2 qa1 = *(const ulonglong2*)(sA + k * SAW + ptg * 8 + 4);
            const ull a2[4] = { qa0.x, qa0.y, qa1.x, qa1.y };
            const float4 wv = *(const float4*)(sW + k * OUTC + ocg * 4);
            ull w2[4];
            PACK2(w2[0], __float_as_uint(wv.x));
            PACK2(w2[1], __float_as_uint(wv.y));
            PACK2(w2[2], __float_as_uint(wv.z));
            PACK2(w2[3], __float_as_uint(wv.w));
#pragma unroll
            for (int i = 0; i < 4; i++)
#pragma unroll
                for (int j = 0; j < 4; j++)
                    FMA2(acc[i][j], a2[j], w2[i], acc[i][j]);
        }

        if (c < CKD / KCH - 1) {
            __syncthreads();
#pragma unroll
            for (int i = 0; i < 4; i++) {
                sA[(kqA[i] * 4 + 0) * SAW + ptA[i]] = pa[i].x;
                sA[(kqA[i] * 4 + 1) * SAW + ptA[i]] = pa[i].y;
                sA[(kqA[i] * 4 + 2) * SAW + ptA[i]] = pa[i].z;
                sA[(kqA[i] * 4 + 3) * SAW + ptA[i]] = pa[i].w;
                ((float4*)sW)[i * 128 + tid] = pw[i];
            }
            __syncthreads();
        }
    }

#pragma unroll
    for (int i = 0; i < 4; i++) {
        const int oc = ocg * 4 + i;
        const float bv = __ldg(bias + oc);
        const size_t rowo = ((size_t)b * OUTC + oc) * NN + nbase + ptg * 8;
#pragma unroll
        for (int j = 0; j < 4; j++) {
            unsigned int lo, hi;
            UNPACK2(lo, hi, acc[i][j]);
            float v0 = __uint_as_float(lo) + bv;
            float v1 = __uint_as_float(hi) + bv;
            v0 = (v0 > 0.f) ? v0 : 0.2f * v0;
            v1 = (v1 > 0.f) ? v1 : 0.2f * v1;
            const float2 fr = *(const float2*)(feat_orig + rowo + 2 * j);
            *(float2*)(out + rowo + 2 * j) = make_float2(v0 + fr.x, v1 + fr.y);
        }
    }
}

// ---------------------------------------------------------------------------
extern "C" void kernel_launch(void* const* d_in, const int* in_sizes, int n_in,
                              void* d_out, int out_size) {
    const float* x       = (const float*)d_in[0];
    const float* feature = (const float*)d_in[1];
    const void*  neigh   = d_in[2];
    const float* kern    = (const float*)d_in[3];
    const float* conv_w  = (const float*)d_in[4];
    const float* conv_b  = (const float*)d_in[5];
    float*       out     = (float*)d_out;

    prep_k<<<TBLK + MBLK + 1, 256>>>(feature, x, conv_w, (const int*)neigh);

    agg_k<<<BB * NN / 32, 256>>>(neigh, kern);

    gemm_k<<<BB * NN / 64, 128>>>(conv_b, feature, out);
}

// round 16
// speedup vs baseline: 2.1304x; 1.3960x over previous
#include <cuda_runtime.h>
#include <cstdint>

// Problem constants
#define BB   8
#define CC   64
#define NN   4096
#define KK   20
#define MM   8
#define OUTC 64
#define CKD  512      // C*M

// Scratch (device globals: allocation-free). 16B-aligned.
__device__ __align__(16) float g_featT[BB * NN * CC];   // (B,N,C)
__device__ __align__(16) float g_xT[BB * NN * 3];       // (B,N,3)
__device__ __align__(16) float g_agg[BB * NN * CKD];    // (B*N, 512) agg rows
__device__ int g_is64;                                  // neigh dtype flag

// ---------------------------------------------------------------------------
// PTX helpers (baseline ISA only — no arch-suffix-gated instructions)
// ---------------------------------------------------------------------------
__device__ __forceinline__ uint32_t smem_u32(const void* p) {
    uint32_t a;
    asm("{ .reg .u64 t; cvta.to.shared.u64 t, %1; cvt.u32.u64 %0, t; }"
        : "=r"(a) : "l"(p));
    return a;
}
__device__ __forceinline__ uint32_t f2tf(float f) {
    uint32_t r;
    asm("cvt.rna.tf32.f32 %0, %1;" : "=r"(r) : "f"(f));
    return r;
}
#define CPA16(dst, src) \
    asm volatile("cp.async.cg.shared.global [%0], [%1], 16;" :: "r"(dst), "l"(src))
#define CPA_COMMIT() asm volatile("cp.async.commit_group;" ::: "memory")
#define CPA_WAIT(n)  asm volatile("cp.async.wait_group %0;" :: "n"(n) : "memory")

#define MMA_TF32(c0,c1,c2,c3, a0,a1,a2,a3, b0,b1) \
    asm volatile( \
        "mma.sync.aligned.m16n8k8.row.col.f32.tf32.tf32.f32 " \
        "{%0,%1,%2,%3}, {%4,%5,%6,%7}, {%8,%9}, {%0,%1,%2,%3};" \
        : "+f"(c0), "+f"(c1), "+f"(c2), "+f"(c3) \
        : "r"(a0), "r"(a1), "r"(a2), "r"(a3), "r"(b0), "r"(b1))

// ---------------------------------------------------------------------------
// Kernel 1 (prep, fused): role dispatch by blockIdx.x
//   [0, 2048)     : transpose feature (B,C,N)->(B,N,C), 32x32 tiles
//   [2048, 2176)  : x (B,3,N)->(B,N,3)
//   [2176]        : neigh dtype probe
// ---------------------------------------------------------------------------
#define TBLK 2048
#define XBLK 128

__global__ __launch_bounds__(256) void prep_k(
    const float* __restrict__ f,
    const float* __restrict__ x,
    const int*   __restrict__ nw)
{
    __shared__ float tile[32][33];
    __shared__ int any_nonzero;
    const int bidx = blockIdx.x;
    const int tid  = threadIdx.x;

    if (bidx < TBLK) {
        const int bx = bidx & 127, by = (bidx >> 7) & 1, bz = bidx >> 8;
        const int n0 = bx * 32, c0 = by * 32;
        const int tx = tid & 31, ty = tid >> 5;
#pragma unroll
        for (int i = ty; i < 32; i += 8)
            tile[i][tx] = f[((size_t)bz * CC + c0 + i) * NN + n0 + tx];
        __syncthreads();
#pragma unroll
        for (int i = ty; i < 32; i += 8)
            g_featT[((size_t)bz * NN + n0 + i) * CC + c0 + tx] = tile[tx][i];
    } else if (bidx < TBLK + XBLK) {
        const int t = (bidx - TBLK) * 256 + tid;
        const int b = t / NN, n = t % NN;
#pragma unroll
        for (int c = 0; c < 3; c++)
            g_xT[(size_t)t * 3 + c] = x[((size_t)b * 3 + c) * NN + n];
    } else {
        if (tid == 0) any_nonzero = 0;
        __syncthreads();
        int nz = 0;
#pragma unroll
        for (int i = 0; i < 4; i++) {
            const int wv = nw[2 * (tid + 256 * i) + 1];
            nz |= (wv != 0);
        }
        if (nz) atomicOr(&any_nonzero, 1);
        __syncthreads();
        if (tid == 0) g_is64 = any_nonzero ? 0 : 1;
    }
}

// ---------------------------------------------------------------------------
// Kernel 2 (agg): unchanged (R12-proven). One warp = 4 points as 2 pairs.
// ---------------------------------------------------------------------------
__global__ __launch_bounds__(256, 4) void agg_k(
    const void* __restrict__ neigh_raw,
    const float* __restrict__ kern)
{
    __shared__ __align__(16) float psW[8][2][KK * MM];
    __shared__ int   sj[8][2][KK];
    __shared__ float kerS[24];

    const int tid  = threadIdx.x;
    const int warp = tid >> 5, lane = tid & 31;

    if (tid < 24) kerS[tid] = kern[tid];
    __syncthreads();

    const int is64 = g_is64;
    const long long* n64 = (const long long*)neigh_raw;
    const int*       n32 = (const int*)neigh_raw;

    float* psM0 = psW[warp][0];
    float* psM1 = psW[warp][1];
    int*   sj0  = sj[warp][0];
    int*   sj1  = sj[warp][1];

    for (int pp = 0; pp < 2; pp++) {
        const int ng0 = blockIdx.x * 32 + warp * 4 + pp * 2;
        const int ng1 = ng0 + 1;
        const int b   = ng0 >> 12;
        const float* fbase = g_featT + (size_t)b * NN * CC;

        int j0 = 0, j1 = 0;
        if (lane < KK) {
            const size_t pos0 = (size_t)ng0 * KK + lane;
            const size_t pos1 = (size_t)ng1 * KK + lane;
            j0 = is64 ? (int)n64[pos0] : n32[pos0];
            j1 = is64 ? (int)n64[pos1] : n32[pos1];
            j0 &= (NN - 1); j1 &= (NN - 1);
            sj0[lane] = j0; sj1[lane] = j1;
        }

        float a0 = 0.f, a1 = 0.f, a2 = 0.f;
        float b0 = 0.f, b1 = 0.f, b2 = 0.f;
        if (lane < KK) {
            const float* xp0 = g_xT + ((size_t)b * NN + j0) * 3;
            const float* xp1 = g_xT + ((size_t)b * NN + j1) * 3;
            a0 = xp0[0]; a1 = xp0[1]; a2 = xp0[2];
            b0 = xp1[0]; b1 = xp1[1]; b2 = xp1[2];
        }
        const float ca0 = __shfl_sync(0xFFFFFFFFu, a0, 0);
        const float ca1 = __shfl_sync(0xFFFFFFFFu, a1, 0);
        const float ca2 = __shfl_sync(0xFFFFFFFFu, a2, 0);
        const float cb0 = __shfl_sync(0xFFFFFFFFu, b0, 0);
        const float cb1 = __shfl_sync(0xFFFFFFFFu, b1, 0);
        const float cb2 = __shfl_sync(0xFFFFFFFFu, b2, 0);
        a0 -= ca0; a1 -= ca1; a2 -= ca2;
        b0 -= cb0; b1 -= cb1; b2 -= cb2;

        float pr0[MM], pr1[MM];
#pragma unroll
        for (int m = 0; m < MM; m++) {
            pr0[m] = a0 * kerS[m] + a1 * kerS[MM + m] + a2 * kerS[2 * MM + m];
            pr1[m] = b0 * kerS[m] + b1 * kerS[MM + m] + b2 * kerS[2 * MM + m];
        }
        if (lane == 0) { pr0[0] += 1.0f; pr1[0] += 1.0f; }

#pragma unroll
        for (int m = 0; m < MM; m++) {
            float e0 = (lane < KK) ? __expf(pr0[m]) : 0.f;
            float e1 = (lane < KK) ? __expf(pr1[m]) : 0.f;
            float s0 = e0, s1 = e1;
#pragma unroll
            for (int o = 16; o; o >>= 1) {
                s0 += __shfl_xor_sync(0xFFFFFFFFu, s0, o);
                s1 += __shfl_xor_sync(0xFFFFFFFFu, s1, o);
            }
            pr0[m] = e0 / s0;
            pr1[m] = e1 / s1;
        }
        if (lane < KK) {
#pragma unroll
            for (int m = 0; m < MM; m++) {
                psM0[lane * MM + m] = pr0[m];
                psM1[lane * MM + m] = pr1[m];
            }
        }
        __syncwarp();

        float accA0[MM], accB0[MM], accA1[MM], accB1[MM];
#pragma unroll
        for (int m = 0; m < MM; m++) {
            accA0[m] = 0.f; accB0[m] = 0.f; accA1[m] = 0.f; accB1[m] = 0.f;
        }

#pragma unroll 4
        for (int k = 0; k < KK; k++) {
            const int jk0 = sj0[k];
            const int jk1 = sj1[k];
            const float2 fv0 = *(const float2*)(fbase + (size_t)jk0 * CC + 2 * lane);
            const float2 fv1 = *(const float2*)(fbase + (size_t)jk1 * CC + 2 * lane);
            const float4 pA0 = *(const float4*)(psM0 + k * MM);
            const float4 pB0 = *(const float4*)(psM0 + k * MM + 4);
            const float4 pA1 = *(const float4*)(psM1 + k * MM);
            const float4 pB1 = *(const float4*)(psM1 + k * MM + 4);
            accA0[0] = fmaf(fv0.x, pA0.x, accA0[0]); accA0[1] = fmaf(fv0.x, pA0.y, accA0[1]);
            accA0[2] = fmaf(fv0.x, pA0.z, accA0[2]); accA0[3] = fmaf(fv0.x, pA0.w, accA0[3]);
            accA0[4] = fmaf(fv0.x, pB0.x, accA0[4]); accA0[5] = fmaf(fv0.x, pB0.y, accA0[5]);
            accA0[6] = fmaf(fv0.x, pB0.z, accA0[6]); accA0[7] = fmaf(fv0.x, pB0.w, accA0[7]);
            accB0[0] = fmaf(fv0.y, pA0.x, accB0[0]); accB0[1] = fmaf(fv0.y, pA0.y, accB0[1]);
            accB0[2] = fmaf(fv0.y, pA0.z, accB0[2]); accB0[3] = fmaf(fv0.y, pA0.w, accB0[3]);
            accB0[4] = fmaf(fv0.y, pB0.x, accB0[4]); accB0[5] = fmaf(fv0.y, pB0.y, accB0[5]);
            accB0[6] = fmaf(fv0.y, pB0.z, accB0[6]); accB0[7] = fmaf(fv0.y, pB0.w, accB0[7]);
            accA1[0] = fmaf(fv1.x, pA1.x, accA1[0]); accA1[1] = fmaf(fv1.x, pA1.y, accA1[1]);
            accA1[2] = fmaf(fv1.x, pA1.z, accA1[2]); accA1[3] = fmaf(fv1.x, pA1.w, accA1[3]);
            accA1[4] = fmaf(fv1.x, pB1.x, accA1[4]); accA1[5] = fmaf(fv1.x, pB1.y, accA1[5]);
            accA1[6] = fmaf(fv1.x, pB1.z, accA1[6]); accA1[7] = fmaf(fv1.x, pB1.w, accA1[7]);
            accB1[0] = fmaf(fv1.y, pA1.x, accB1[0]); accB1[1] = fmaf(fv1.y, pA1.y, accB1[1]);
            accB1[2] = fmaf(fv1.y, pA1.z, accB1[2]); accB1[3] = fmaf(fv1.y, pA1.w, accB1[3]);
            accB1[4] = fmaf(fv1.y, pB1.x, accB1[4]); accB1[5] = fmaf(fv1.y, pB1.y, accB1[5]);
            accB1[6] = fmaf(fv1.y, pB1.z, accB1[6]); accB1[7] = fmaf(fv1.y, pB1.w, accB1[7]);
        }

        float* ar0 = g_agg + (size_t)ng0 * CKD + lane * 16;
        float* ar1 = g_agg + (size_t)ng1 * CKD + lane * 16;
        *(float4*)(ar0 + 0)  = make_float4(accA0[0], accA0[1], accA0[2], accA0[3]);
        *(float4*)(ar0 + 4)  = make_float4(accA0[4], accA0[5], accA0[6], accA0[7]);
        *(float4*)(ar0 + 8)  = make_float4(accB0[0], accB0[1], accB0[2], accB0[3]);
        *(float4*)(ar0 + 12) = make_float4(accB0[4], accB0[5], accB0[6], accB0[7]);
        *(float4*)(ar1 + 0)  = make_float4(accA1[0], accA1[1], accA1[2], accA1[3]);
        *(float4*)(ar1 + 4)  = make_float4(accA1[4], accA1[5], accA1[6], accA1[7]);
        *(float4*)(ar1 + 8)  = make_float4(accB1[0], accB1[1], accB1[2], accB1[3]);
        *(float4*)(ar1 + 12) = make_float4(accB1[4], accB1[5], accB1[6], accB1[7]);
        __syncwarp();
    }
}

// ---------------------------------------------------------------------------
// Kernel 3 (GEMM via mma.sync tf32, legacy tensor path — compiles for sm_103):
// D(128pt x 64oc) = A(128x512) @ B(64x512)^T per CTA.
// 256 CTAs x 128 thr (4 warps). Warp tile 32pt x 64oc (2 m-tiles x 8 n-tiles).
// K chunked by 32, cp.async double-buffered staging of raw fp32; fragments
// loaded from conflict-free stride-36 smem and cvt.rna'd to tf32 in regs.
// Epilogue via shared sC for fully coalesced (B,OC,N) stores.
// ---------------------------------------------------------------------------
#define KCHT  32
#define NCH   (CKD / KCHT)          // 16
#define ASTR  36                    // A/B smem row stride in floats
#define A_FL  (128 * ASTR)          // 4608 floats
#define B_FL  (64 * ASTR)           // 2304 floats
#define STG_FL (A_FL + B_FL)        // 6912 floats per stage
#define SM_BYTES (2 * STG_FL * 4)   // 55296 bytes (sC 128*66*4=33792 fits)

__global__ __launch_bounds__(128) void gemm_mma_k(
    const float* __restrict__ w,      // conv_w (64 x 512), used directly as B
    const float* __restrict__ bias,
    const float* __restrict__ feat_orig,
    float* __restrict__ out)
{
    extern __shared__ float smf[];
    const uint32_t sbase = smem_u32(smf);

    const int tid  = threadIdx.x;
    const int wid  = tid >> 5;
    const int lane = tid & 31;
    const int gid  = lane >> 2;       // groupID
    const int tg   = lane & 3;        // threadID_in_group

    const int pbase = blockIdx.x * 128;
    const int b     = pbase >> 12;
    const int nbase = pbase & (NN - 1);

    float acc[2][8][4];
#pragma unroll
    for (int mt = 0; mt < 2; mt++)
#pragma unroll
        for (int nt = 0; nt < 8; nt++)
#pragma unroll
            for (int i = 0; i < 4; i++) acc[mt][nt][i] = 0.f;

    // cp.async staging: A = 1024 16B slots (8/thr), B = 512 slots (4/thr)
    auto stage = [&](int kc, int buf) {
        const uint32_t sA = sbase + (uint32_t)buf * STG_FL * 4;
        const uint32_t sB = sA + A_FL * 4;
#pragma unroll
        for (int i = 0; i < 8; i++) {
            const int s  = i * 128 + tid;
            const int pt = s >> 3, kq = s & 7;
            CPA16(sA + (pt * ASTR + kq * 4) * 4,
                  g_agg + (size_t)(pbase + pt) * CKD + kc + kq * 4);
        }
#pragma unroll
        for (int i = 0; i < 4; i++) {
            const int s  = i * 128 + tid;
            const int oc = s >> 3, kq = s & 7;
            CPA16(sB + (oc * ASTR + kq * 4) * 4,
                  w + (size_t)oc * CKD + kc + kq * 4);
        }
        CPA_COMMIT();
    };

    stage(0, 0);

    for (int c = 0; c < NCH; c++) {
        if (c < NCH - 1) { stage((c + 1) * KCHT, (c + 1) & 1); CPA_WAIT(1); }
        else             { CPA_WAIT(0); }
        __syncthreads();

        const float* A = smf + (c & 1) * STG_FL;
        const float* B = A + A_FL;

#pragma unroll
        for (int k8 = 0; k8 < 4; k8++) {
            const int kb = k8 * 8;

            uint32_t af[2][4];
#pragma unroll
            for (int mt = 0; mt < 2; mt++) {
                const int r0 = wid * 32 + mt * 16 + gid;
                af[mt][0] = f2tf(A[(r0)     * ASTR + kb + tg]);
                af[mt][1] = f2tf(A[(r0 + 8) * ASTR + kb + tg]);
                af[mt][2] = f2tf(A[(r0)     * ASTR + kb + tg + 4]);
                af[mt][3] = f2tf(A[(r0 + 8) * ASTR + kb + tg + 4]);
            }
            uint32_t bf[8][2];
#pragma unroll
            for (int nt = 0; nt < 8; nt++) {
                const int n = nt * 8 + gid;
                bf[nt][0] = f2tf(B[n * ASTR + kb + tg]);
                bf[nt][1] = f2tf(B[n * ASTR + kb + tg + 4]);
            }
#pragma unroll
            for (int mt = 0; mt < 2; mt++)
#pragma unroll
                for (int nt = 0; nt < 8; nt++)
                    MMA_TF32(acc[mt][nt][0], acc[mt][nt][1], acc[mt][nt][2], acc[mt][nt][3],
                             af[mt][0], af[mt][1], af[mt][2], af[mt][3],
                             bf[nt][0], bf[nt][1]);
        }
        __syncthreads();
    }

    // -------- epilogue: accs -> shared sC[pt][oc] (stride 66), then coalesced
    float* sC = smf;
#pragma unroll
    for (int mt = 0; mt < 2; mt++) {
        const int r0 = wid * 32 + mt * 16 + gid;
#pragma unroll
        for (int nt = 0; nt < 8; nt++) {
            const int col = nt * 8 + tg * 2;
            *(float2*)(sC + (r0)     * 66 + col) = make_float2(acc[mt][nt][0], acc[mt][nt][1]);
            *(float2*)(sC + (r0 + 8) * 66 + col) = make_float2(acc[mt][nt][2], acc[mt][nt][3]);
        }
    }
    __syncthreads();

    const int n = nbase + tid;
#pragma unroll 8
    for (int oc = 0; oc < OUTC; oc++) {
        float v = sC[tid * 66 + oc] + __ldg(bias + oc);
        v = (v > 0.f) ? v : 0.2f * v;
        const size_t o = ((size_t)b * OUTC + oc) * NN + n;
        out[o] = v + __ldg(feat_orig + o);
    }
}

// ---------------------------------------------------------------------------
extern "C" void kernel_launch(void* const* d_in, const int* in_sizes, int n_in,
                              void* d_out, int out_size) {
    const float* x       = (const float*)d_in[0];
    const float* feature = (const float*)d_in[1];
    const void*  neigh   = d_in[2];
    const float* kern    = (const float*)d_in[3];
    const float* conv_w  = (const float*)d_in[4];
    const float* conv_b  = (const float*)d_in[5];
    float*       out     = (float*)d_out;

    cudaFuncSetAttribute(gemm_mma_k,
                         cudaFuncAttributeMaxDynamicSharedMemorySize, SM_BYTES);

    prep_k<<<TBLK + XBLK + 1, 256>>>(feature, x, (const int*)neigh);

    agg_k<<<BB * NN / 32, 256>>>(neigh, kern);

    gemm_mma_k<<<BB * NN / 128, 128, SM_BYTES>>>(conv_w, conv_b, feature, out);
}